// round 1
// baseline (speedup 1.0000x reference)
#include <cuda_runtime.h>
#include <cuda_bf16.h>
#include <math.h>

// ---------------------------------------------------------------------------
// Problem constants
// ---------------------------------------------------------------------------
#define BB      2
#define II      2048
#define JJ      16
#define NKK     2048
#define DMODEL  256
#define DHIDDEN 512
#define HH      8
#define DK      64

#define ROWS_BI   (BB * II)            // 4096
#define ROWS_BIJ  (BB * II * JJ)       // 65536

// ---------------------------------------------------------------------------
// Scratch (device globals — no allocation allowed)
// ---------------------------------------------------------------------------
__device__ float g_qh[ROWS_BI * DHIDDEN];          // 8 MB   q @ Wq
__device__ float g_kv[ROWS_BI * 2 * DHIDDEN];      // 16 MB  k @ Wkv  (kk | vv)
__device__ float g_hidden[(size_t)ROWS_BIJ * DHIDDEN];     // 128 MB relu(pos@W1+b1)
__device__ float g_poskv[(size_t)ROWS_BIJ * 2 * DHIDDEN];  // 256 MB hidden@W2+b2
__device__ float g_agg[ROWS_BI * DHIDDEN];         // 8 MB   attention output
__device__ int   g_idx_is64;

// ---------------------------------------------------------------------------
// local_idx dtype detection: jnp.int64 downcasts to int32 unless x64 enabled.
// If the data is真 int64, every sampled 64-bit word is a value in [0, NK).
// If it is int32, a sampled 64-bit word is lo + hi*2^32 with hi uniform in
// [0,2048) -> P(all 64 samples < 2048) ~ 2048^-64.
// ---------------------------------------------------------------------------
__global__ void detect_idx_kernel(const void* idx_raw) {
    if (threadIdx.x == 0 && blockIdx.x == 0) {
        const long long* p = (const long long*)idx_raw;
        int is64 = 1;
        for (int s = 0; s < 64; s++) {
            long long v = p[s * 37];   // max offset 2331 < 32768 (int64 view)
            if (v < 0 || v >= NKK) { is64 = 0; break; }
        }
        g_idx_is64 = is64;
    }
}

// ---------------------------------------------------------------------------
// Generic row-major fp32 GEMM: C[M,N] = act(A[M,K] @ B[K,N] + bias)
// BM=BN=128, BK=16, 256 threads, 8x8 per-thread microtile.
// All M,N,K used here are multiples of the tile sizes.
// ---------------------------------------------------------------------------
#define GBM 128
#define GBN 128
#define GBK 16
#define GTM 8
#define GTN 8

__global__ __launch_bounds__(256) void gemm_kernel(
    const float* __restrict__ A, const float* __restrict__ B,
    const float* __restrict__ bias, float* __restrict__ C,
    int M, int N, int K, int do_relu)
{
    __shared__ float As[GBK][GBM];   // A stored transposed
    __shared__ float Bs[GBK][GBN];

    const int tid = threadIdx.x;
    const int tx  = tid & 15;        // 0..15  -> N direction
    const int ty  = tid >> 4;        // 0..15  -> M direction
    const int block_row = blockIdx.y * GBM;
    const int block_col = blockIdx.x * GBN;

    float acc[GTM][GTN];
    #pragma unroll
    for (int i = 0; i < GTM; i++)
        #pragma unroll
        for (int j = 0; j < GTN; j++) acc[i][j] = 0.0f;

    for (int k0 = 0; k0 < K; k0 += GBK) {
        // load A tile (128x16) and B tile (16x128), 2 float4 each per thread
        #pragma unroll
        for (int l = 0; l < 2; l++) {
            int a_id = tid + l * 256;            // 0..511
            int ar = a_id >> 2;                  // 0..127
            int ac = (a_id & 3) << 2;            // 0,4,8,12
            float4 va = *(const float4*)(A + (size_t)(block_row + ar) * K + k0 + ac);
            As[ac + 0][ar] = va.x;
            As[ac + 1][ar] = va.y;
            As[ac + 2][ar] = va.z;
            As[ac + 3][ar] = va.w;

            int b_id = tid + l * 256;
            int br = b_id >> 5;                  // 0..15
            int bc = (b_id & 31) << 2;           // 0..124
            *(float4*)(&Bs[br][bc]) =
                *(const float4*)(B + (size_t)(k0 + br) * N + block_col + bc);
        }
        __syncthreads();

        #pragma unroll
        for (int k = 0; k < GBK; k++) {
            float a[GTM], b[GTN];
            #pragma unroll
            for (int i = 0; i < GTM; i += 4)
                *(float4*)(&a[i]) = *(const float4*)(&As[k][ty * GTM + i]);
            #pragma unroll
            for (int j = 0; j < GTN; j += 4)
                *(float4*)(&b[j]) = *(const float4*)(&Bs[k][tx * GTN + j]);
            #pragma unroll
            for (int i = 0; i < GTM; i++)
                #pragma unroll
                for (int j = 0; j < GTN; j++)
                    acc[i][j] = fmaf(a[i], b[j], acc[i][j]);
        }
        __syncthreads();
    }

    // epilogue
    float bvals[GTN];
    #pragma unroll
    for (int j = 0; j < GTN; j++)
        bvals[j] = bias ? bias[block_col + tx * GTN + j] : 0.0f;

    #pragma unroll
    for (int i = 0; i < GTM; i++) {
        int r = block_row + ty * GTM + i;
        float* crow = C + (size_t)r * N + block_col + tx * GTN;
        #pragma unroll
        for (int j = 0; j < GTN; j += 4) {
            float4 v;
            v.x = acc[i][j + 0] + bvals[j + 0];
            v.y = acc[i][j + 1] + bvals[j + 1];
            v.z = acc[i][j + 2] + bvals[j + 2];
            v.w = acc[i][j + 3] + bvals[j + 3];
            if (do_relu) {
                v.x = fmaxf(v.x, 0.0f); v.y = fmaxf(v.y, 0.0f);
                v.z = fmaxf(v.z, 0.0f); v.w = fmaxf(v.w, 0.0f);
            }
            *(float4*)(crow + j) = v;
        }
    }
}

// ---------------------------------------------------------------------------
// Fused gather + attention per (b,i) row. One CTA of 256 threads per row.
//   logits[j,h] = scale * sum_d qh[h,d] * (kk[idx_j, h*64+d] + pos_k[j,h,d])
//   attn = softmax_j(logits)
//   agg[h,d]    = sum_j attn[j,h] * (vv[idx_j, h*64+d] + pos_v[j,h,d])
// kv layout: [4096, 1024] rows, kk = cols [0,512), vv = cols [512,1024)
// poskv layout: [65536, 1024], per head h: pos_k at h*128+d, pos_v at h*128+64+d
// ---------------------------------------------------------------------------
__global__ __launch_bounds__(256) void attn_kernel(
    const float* __restrict__ qh, const float* __restrict__ kvb,
    const float* __restrict__ poskv, const void* __restrict__ idx_raw,
    float* __restrict__ agg)
{
    __shared__ float qv[DHIDDEN];
    __shared__ int   sidx[JJ];
    __shared__ float logit[JJ][HH];
    __shared__ float attnw[JJ][HH];

    const int row = blockIdx.x;       // b*I + i
    const int b   = row >> 11;        // I = 2048
    const int t   = threadIdx.x;

    if (t < JJ) {
        long long n;
        if (g_idx_is64) n = ((const long long*)idx_raw)[(size_t)row * JJ + t];
        else            n = ((const int*)idx_raw)[(size_t)row * JJ + t];
        sidx[t] = b * NKK + (int)n;
    }
    qv[t]       = qh[(size_t)row * DHIDDEN + t];
    qv[t + 256] = qh[(size_t)row * DHIDDEN + t + 256];
    __syncthreads();

    // phase 1: logits (128 threads; (j,h) pair each)
    if (t < JJ * HH) {
        int j = t >> 3, h = t & 7;
        const float* kp = kvb   + (size_t)sidx[j] * 1024 + h * 64;
        const float* pp = poskv + ((size_t)row * JJ + j) * 1024 + h * 128;
        const float* qp = qv + h * 64;
        float s = 0.0f;
        #pragma unroll
        for (int d = 0; d < DK; d += 4) {
            float4 kk4 = *(const float4*)(kp + d);
            float4 pk4 = *(const float4*)(pp + d);
            s = fmaf(qp[d + 0], kk4.x + pk4.x, s);
            s = fmaf(qp[d + 1], kk4.y + pk4.y, s);
            s = fmaf(qp[d + 2], kk4.z + pk4.z, s);
            s = fmaf(qp[d + 3], kk4.w + pk4.w, s);
        }
        logit[j][h] = s * 0.125f;     // D_K^-0.5 = 1/8
    }
    __syncthreads();

    // phase 2: softmax over j, per head (8 threads)
    if (t < HH) {
        float m = -1e30f;
        #pragma unroll
        for (int j = 0; j < JJ; j++) m = fmaxf(m, logit[j][t]);
        float ssum = 0.0f;
        #pragma unroll
        for (int j = 0; j < JJ; j++) {
            float e = expf(logit[j][t] - m);
            attnw[j][t] = e;
            ssum += e;
        }
        float inv = 1.0f / ssum;
        #pragma unroll
        for (int j = 0; j < JJ; j++) attnw[j][t] *= inv;
    }
    __syncthreads();

    // phase 3: aggregate values (each thread handles 2 of 512 outputs)
    #pragma unroll
    for (int o0 = 0; o0 < DHIDDEN; o0 += 256) {
        int o = o0 + t;
        int h = o >> 6, d = o & 63;
        float a = 0.0f;
        #pragma unroll
        for (int j = 0; j < JJ; j++) {
            float w = attnw[j][h];
            float vvv = kvb[(size_t)sidx[j] * 1024 + 512 + h * 64 + d]
                      + poskv[((size_t)row * JJ + j) * 1024 + h * 128 + 64 + d];
            a = fmaf(w, vvv, a);
        }
        agg[(size_t)row * DHIDDEN + o] = a;
    }
}

// ---------------------------------------------------------------------------
// Launch
// inputs: 0:q 1:k 2:pos 3:local_idx 4:Wq 5:Wkv 6:W1 7:b1 8:W2 9:b2 10:Wout
// ---------------------------------------------------------------------------
extern "C" void kernel_launch(void* const* d_in, const int* in_sizes, int n_in,
                              void* d_out, int out_size)
{
    const float* q    = (const float*)d_in[0];
    const float* k    = (const float*)d_in[1];
    const float* pos  = (const float*)d_in[2];
    const void*  lidx = d_in[3];
    const float* Wq   = (const float*)d_in[4];
    const float* Wkv  = (const float*)d_in[5];
    const float* W1   = (const float*)d_in[6];
    const float* b1   = (const float*)d_in[7];
    const float* W2   = (const float*)d_in[8];
    const float* b2   = (const float*)d_in[9];
    const float* Wout = (const float*)d_in[10];
    float* out = (float*)d_out;

    float *qh, *kv, *hidden, *poskv, *agg;
    cudaGetSymbolAddress((void**)&qh,     g_qh);
    cudaGetSymbolAddress((void**)&kv,     g_kv);
    cudaGetSymbolAddress((void**)&hidden, g_hidden);
    cudaGetSymbolAddress((void**)&poskv,  g_poskv);
    cudaGetSymbolAddress((void**)&agg,    g_agg);

    detect_idx_kernel<<<1, 32>>>(lidx);

    // qh = q @ Wq                     [4096,512]  K=256
    gemm_kernel<<<dim3(DHIDDEN / GBN, ROWS_BI / GBM), 256>>>(
        q, Wq, nullptr, qh, ROWS_BI, DHIDDEN, DMODEL, 0);

    // kv = k @ Wkv                    [4096,1024] K=256
    gemm_kernel<<<dim3(2 * DHIDDEN / GBN, ROWS_BI / GBM), 256>>>(
        k, Wkv, nullptr, kv, ROWS_BI, 2 * DHIDDEN, DMODEL, 0);

    // hidden = relu(pos @ W1 + b1)    [65536,512] K=512
    gemm_kernel<<<dim3(DHIDDEN / GBN, ROWS_BIJ / GBM), 256>>>(
        pos, W1, b1, hidden, ROWS_BIJ, DHIDDEN, DHIDDEN, 1);

    // poskv = hidden @ W2 + b2        [65536,1024] K=512
    gemm_kernel<<<dim3(2 * DHIDDEN / GBN, ROWS_BIJ / GBM), 256>>>(
        hidden, W2, b2, poskv, ROWS_BIJ, 2 * DHIDDEN, DHIDDEN, 0);

    // gather + attention -> agg       [4096,512]
    attn_kernel<<<ROWS_BI, 256>>>(qh, kv, poskv, lidx, agg);

    // out = agg @ Wout                [4096,256] K=512
    gemm_kernel<<<dim3(DMODEL / GBN, ROWS_BI / GBM), 256>>>(
        agg, Wout, nullptr, out, ROWS_BI, DMODEL, DHIDDEN, 0);
}

// round 3
// speedup vs baseline: 2.2112x; 2.2112x over previous
#include <cuda_runtime.h>
#include <cuda_bf16.h>
#include <math.h>
#include <stdint.h>

// ---------------------------------------------------------------------------
// Problem constants
// ---------------------------------------------------------------------------
#define BB      2
#define II      2048
#define JJ      16
#define NKK     2048
#define DMODEL  256
#define DHIDDEN 512
#define HH      8
#define DK      64

#define ROWS_BI   (BB * II)            // 4096
#define ROWS_BIJ  (BB * II * JJ)       // 65536

// ---------------------------------------------------------------------------
// Scratch (device globals — no allocation allowed)
// ---------------------------------------------------------------------------
__device__ __nv_bfloat16 g_qs_hi[ROWS_BI * DMODEL];
__device__ __nv_bfloat16 g_qs_lo[ROWS_BI * DMODEL];
__device__ __nv_bfloat16 g_ks_hi[ROWS_BI * DMODEL];
__device__ __nv_bfloat16 g_ks_lo[ROWS_BI * DMODEL];
__device__ __nv_bfloat16 g_ps_hi[(size_t)ROWS_BIJ * DHIDDEN];   // 64 MB
__device__ __nv_bfloat16 g_ps_lo[(size_t)ROWS_BIJ * DHIDDEN];   // 64 MB
__device__ __nv_bfloat16 g_hid_hi[(size_t)ROWS_BIJ * DHIDDEN];  // 64 MB
__device__ __nv_bfloat16 g_hid_lo[(size_t)ROWS_BIJ * DHIDDEN];  // 64 MB
__device__ __nv_bfloat16 g_agg_hi[ROWS_BI * DHIDDEN];
__device__ __nv_bfloat16 g_agg_lo[ROWS_BI * DHIDDEN];

// transposed split weights, packed: [N,K] layouts
#define WQ_OFF   0
#define WQ_SZ    (DHIDDEN * DMODEL)            // 512*256
#define WKV_OFF  (WQ_OFF + WQ_SZ)
#define WKV_SZ   (2 * DHIDDEN * DMODEL)        // 1024*256
#define W1_OFF   (WKV_OFF + WKV_SZ)
#define W1_SZ    (DHIDDEN * DHIDDEN)           // 512*512
#define W2_OFF   (W1_OFF + W1_SZ)
#define W2_SZ    (2 * DHIDDEN * DHIDDEN)       // 1024*512
#define WOUT_OFF (W2_OFF + W2_SZ)
#define WOUT_SZ  (DMODEL * DHIDDEN)            // 256*512
#define WT_TOTAL (WOUT_OFF + WOUT_SZ)

__device__ __nv_bfloat16 g_wt_hi[WT_TOTAL];
__device__ __nv_bfloat16 g_wt_lo[WT_TOTAL];

__device__ float g_qh[ROWS_BI * DHIDDEN];                  // 8 MB
__device__ float g_kv[ROWS_BI * 2 * DHIDDEN];              // 16 MB
__device__ float g_poskv[(size_t)ROWS_BIJ * 2 * DHIDDEN];  // 256 MB
__device__ int   g_idx_is64;

// ---------------------------------------------------------------------------
// local_idx dtype detection (jnp.int64 usually downcast to int32)
// ---------------------------------------------------------------------------
__global__ void detect_idx_kernel(const void* idx_raw) {
    if (threadIdx.x == 0 && blockIdx.x == 0) {
        const long long* p = (const long long*)idx_raw;
        int is64 = 1;
        for (int s = 0; s < 64; s++) {
            long long v = p[s * 37];
            if (v < 0 || v >= NKK) { is64 = 0; break; }
        }
        g_idx_is64 = is64;
    }
}

// ---------------------------------------------------------------------------
// fp32 -> (bf16 hi, bf16 lo) split, vectorized by 4
// ---------------------------------------------------------------------------
__global__ void split_kernel(const float* __restrict__ x,
                             __nv_bfloat16* __restrict__ hi,
                             __nv_bfloat16* __restrict__ lo, size_t n4)
{
    size_t i = ((size_t)blockIdx.x * blockDim.x + threadIdx.x);
    if (i >= n4) return;
    float4 v = ((const float4*)x)[i];
    __nv_bfloat16 h0 = __float2bfloat16(v.x);
    __nv_bfloat16 h1 = __float2bfloat16(v.y);
    __nv_bfloat16 h2 = __float2bfloat16(v.z);
    __nv_bfloat16 h3 = __float2bfloat16(v.w);
    __nv_bfloat16 l0 = __float2bfloat16(v.x - __bfloat162float(h0));
    __nv_bfloat16 l1 = __float2bfloat16(v.y - __bfloat162float(h1));
    __nv_bfloat16 l2 = __float2bfloat16(v.z - __bfloat162float(h2));
    __nv_bfloat16 l3 = __float2bfloat16(v.w - __bfloat162float(h3));
    __nv_bfloat162* hp = (__nv_bfloat162*)(hi + i * 4);
    __nv_bfloat162* lp = (__nv_bfloat162*)(lo + i * 4);
    hp[0] = __nv_bfloat162(h0, h1); hp[1] = __nv_bfloat162(h2, h3);
    lp[0] = __nv_bfloat162(l0, l1); lp[1] = __nv_bfloat162(l2, l3);
}

// split + transpose weights: W[K,N] -> Wt_hi/lo[N,K]
__global__ void splitT_kernel(const float* __restrict__ W,
                              __nv_bfloat16* __restrict__ thi,
                              __nv_bfloat16* __restrict__ tlo, int K, int N)
{
    int idx = blockIdx.x * 256 + threadIdx.x;
    if (idx >= K * N) return;
    int k = idx / N, n = idx % N;
    float v = W[idx];
    __nv_bfloat16 h = __float2bfloat16(v);
    __nv_bfloat16 l = __float2bfloat16(v - __bfloat162float(h));
    thi[(size_t)n * K + k] = h;
    tlo[(size_t)n * K + k] = l;
}

// ---------------------------------------------------------------------------
// helpers
// ---------------------------------------------------------------------------
__device__ __forceinline__ uint32_t smem_u32(const void* p) {
    uint32_t a;
    asm("{ .reg .u64 t; cvta.to.shared.u64 t, %1; cvt.u32.u64 %0, t; }"
        : "=r"(a) : "l"(p));
    return a;
}

#define SW128(o) ((o) ^ (((o) >> 3) & 0x70))

__device__ __forceinline__ void cp_async16(uint32_t saddr, const void* gaddr) {
    asm volatile("cp.async.cg.shared.global [%0], [%1], 16;"
                 :: "r"(saddr), "l"(gaddr));
}
__device__ __forceinline__ void cp_commit() {
    asm volatile("cp.async.commit_group;");
}

__device__ __forceinline__ void ldsm_x4(uint32_t& a0, uint32_t& a1,
                                        uint32_t& a2, uint32_t& a3, uint32_t addr) {
    asm volatile("ldmatrix.sync.aligned.m8n8.x4.shared.b16 {%0,%1,%2,%3}, [%4];"
                 : "=r"(a0), "=r"(a1), "=r"(a2), "=r"(a3) : "r"(addr));
}
__device__ __forceinline__ void ldsm_x2(uint32_t& b0, uint32_t& b1, uint32_t addr) {
    asm volatile("ldmatrix.sync.aligned.m8n8.x2.shared.b16 {%0,%1}, [%2];"
                 : "=r"(b0), "=r"(b1) : "r"(addr));
}
__device__ __forceinline__ void mma16816(float* c, uint32_t a0, uint32_t a1,
                                         uint32_t a2, uint32_t a3,
                                         uint32_t b0, uint32_t b1) {
    asm volatile(
        "mma.sync.aligned.m16n8k16.row.col.f32.bf16.bf16.f32 "
        "{%0,%1,%2,%3}, {%4,%5,%6,%7}, {%8,%9}, {%0,%1,%2,%3};"
        : "+f"(c[0]), "+f"(c[1]), "+f"(c[2]), "+f"(c[3])
        : "r"(a0), "r"(a1), "r"(a2), "r"(a3), "r"(b0), "r"(b1));
}

// ---------------------------------------------------------------------------
// Tensor-core GEMM via mma.sync (split bf16, 3-term):
//   C[M,N] = A[M,K] @ Wt[N,K]^T (+bias, +relu/split per mode)
// CTA: 128x128 tile, BK=64, 256 threads (8 warps, 2x4 layout, 64x32 per warp),
// cp.async double-buffered SMEM with SW128 swizzle.
// mode 0: fp32 out (+bias optional). mode 1: bias + relu + split bf16 out.
// ---------------------------------------------------------------------------
#define ST_A_HI 0
#define ST_A_LO 16384
#define ST_B_HI 32768
#define ST_B_LO 49152
#define STAGE_BYTES 65536
#define TG_SMEM (1024 + 2 * STAGE_BYTES)

__global__ __launch_bounds__(256) void tgemm_kernel(
    const __nv_bfloat16* __restrict__ Ahi, const __nv_bfloat16* __restrict__ Alo,
    const __nv_bfloat16* __restrict__ Bhi, const __nv_bfloat16* __restrict__ Blo,
    const float* __restrict__ bias,
    float* __restrict__ Cf,
    __nv_bfloat16* __restrict__ Chi, __nv_bfloat16* __restrict__ Clo,
    int M, int N, int K, int mode)
{
    extern __shared__ char smem_raw[];
    uint32_t base0 = smem_u32(smem_raw);
    uint32_t base  = (base0 + 1023) & ~1023u;
    char*    smem  = smem_raw + (base - base0);

    const int tid  = threadIdx.x;
    const int warp = tid >> 5, lane = tid & 31;
    const int wm = warp >> 2, wn = warp & 3;           // 2 x 4 warp grid
    const int rowA0 = blockIdx.y * 128;
    const int rowB0 = blockIdx.x * 128;

    float acc[4][4][4];
    #pragma unroll
    for (int mi = 0; mi < 4; mi++)
        #pragma unroll
        for (int ni = 0; ni < 4; ni++)
            #pragma unroll
            for (int r = 0; r < 4; r++) acc[mi][ni][r] = 0.0f;

    const int nchunks = K >> 6;

    // async chunk loader: 4 sub-tiles (Ahi,Alo,Bhi,Blo), 128 rows x 128B each
    auto load_chunk = [&](int chunk, int stage) {
        const int k0 = chunk << 6;
        uint32_t st = base + stage * STAGE_BYTES;
        #pragma unroll
        for (int l = 0; l < 4; l++) {
            int id = tid + (l << 8);                 // 0..1023
            int r = id >> 3, c = id & 7;
            uint32_t so = SW128((uint32_t)(r * 128 + c * 16));
            size_t ga = (size_t)(rowA0 + r) * K + k0 + (c << 3);
            size_t gb = (size_t)(rowB0 + r) * K + k0 + (c << 3);
            cp_async16(st + ST_A_HI + so, Ahi + ga);
            cp_async16(st + ST_A_LO + so, Alo + ga);
            cp_async16(st + ST_B_HI + so, Bhi + gb);
            cp_async16(st + ST_B_LO + so, Blo + gb);
        }
        cp_commit();
    };

    // fragment address precompute (within a 16KB sub-tile)
    // A (x4): row = wm*64 + mi*16 + (lane&15), colbyte = ks*32 + (lane>>4)*16
    const int a_row_l = (wm << 6) + (lane & 15);
    const int a_cb_l  = (lane >> 4) << 4;
    // B (x2): row = wn*32 + ni*8 + (lane&7), colbyte = ks*32 + ((lane>>3)&1)*16
    const int b_row_l = (wn << 5) + (lane & 7);
    const int b_cb_l  = ((lane >> 3) & 1) << 4;

    load_chunk(0, 0);

    for (int i = 0; i < nchunks; i++) {
        const int s = i & 1;
        if (i + 1 < nchunks) {
            load_chunk(i + 1, 1 - s);
            asm volatile("cp.async.wait_group 1;");
        } else {
            asm volatile("cp.async.wait_group 0;");
        }
        __syncthreads();

        const uint32_t st = base + s * STAGE_BYTES;
        #pragma unroll
        for (int ks = 0; ks < 4; ks++) {
            const int kb = ks << 5;                  // k-step byte offset
            // A hi fragments (shared by the two B terms)
            uint32_t ah[4][4];
            #pragma unroll
            for (int mi = 0; mi < 4; mi++) {
                uint32_t addr = st + ST_A_HI +
                    SW128((uint32_t)((a_row_l + mi * 16) * 128 + kb + a_cb_l));
                ldsm_x4(ah[mi][0], ah[mi][1], ah[mi][2], ah[mi][3], addr);
            }
            // term 1: ah * bh ; term 2: ah * bl
            #pragma unroll
            for (int ni = 0; ni < 4; ni++) {
                uint32_t off = SW128((uint32_t)((b_row_l + ni * 8) * 128 + kb + b_cb_l));
                uint32_t bh0, bh1, bl0, bl1;
                ldsm_x2(bh0, bh1, st + ST_B_HI + off);
                ldsm_x2(bl0, bl1, st + ST_B_LO + off);
                #pragma unroll
                for (int mi = 0; mi < 4; mi++) {
                    mma16816(acc[mi][ni], ah[mi][0], ah[mi][1], ah[mi][2], ah[mi][3], bh0, bh1);
                    mma16816(acc[mi][ni], ah[mi][0], ah[mi][1], ah[mi][2], ah[mi][3], bl0, bl1);
                }
            }
            // term 3: al * bh
            uint32_t al[4][4];
            #pragma unroll
            for (int mi = 0; mi < 4; mi++) {
                uint32_t addr = st + ST_A_LO +
                    SW128((uint32_t)((a_row_l + mi * 16) * 128 + kb + a_cb_l));
                ldsm_x4(al[mi][0], al[mi][1], al[mi][2], al[mi][3], addr);
            }
            #pragma unroll
            for (int ni = 0; ni < 4; ni++) {
                uint32_t off = SW128((uint32_t)((b_row_l + ni * 8) * 128 + kb + b_cb_l));
                uint32_t bh0, bh1;
                ldsm_x2(bh0, bh1, st + ST_B_HI + off);
                #pragma unroll
                for (int mi = 0; mi < 4; mi++)
                    mma16816(acc[mi][ni], al[mi][0], al[mi][1], al[mi][2], al[mi][3], bh0, bh1);
            }
        }
        __syncthreads();
    }

    // ---- epilogue: regs -> SMEM bounce (stride 132 f32) -> global
    float* buf = (float*)smem;
    {
        const int r0 = (wm << 6) + (lane >> 2);
        const int c0 = (wn << 5) + ((lane & 3) << 1);
        #pragma unroll
        for (int mi = 0; mi < 4; mi++) {
            #pragma unroll
            for (int ni = 0; ni < 4; ni++) {
                int rr = r0 + mi * 16;
                int cc = c0 + ni * 8;
                buf[rr * 132 + cc]           = acc[mi][ni][0];
                buf[rr * 132 + cc + 1]       = acc[mi][ni][1];
                buf[(rr + 8) * 132 + cc]     = acc[mi][ni][2];
                buf[(rr + 8) * 132 + cc + 1] = acc[mi][ni][3];
            }
        }
    }
    __syncthreads();

    {
        const int rloc = tid >> 1;
        const int colb = (tid & 1) << 6;            // 0 or 64
        const size_t grow = (size_t)(rowA0 + rloc);
        if (mode == 0) {
            float* crow = Cf + grow * N + rowB0 + colb;
            #pragma unroll
            for (int c = 0; c < 64; c += 4) {
                float4 v = *(float4*)(buf + rloc * 132 + colb + c);
                if (bias) {
                    v.x += bias[rowB0 + colb + c + 0];
                    v.y += bias[rowB0 + colb + c + 1];
                    v.z += bias[rowB0 + colb + c + 2];
                    v.w += bias[rowB0 + colb + c + 3];
                }
                *(float4*)(crow + c) = v;
            }
        } else {
            __nv_bfloat16* hrow = Chi + grow * N + rowB0 + colb;
            __nv_bfloat16* lrow = Clo + grow * N + rowB0 + colb;
            #pragma unroll
            for (int c = 0; c < 64; c += 8) {
                __nv_bfloat16 hv[8], lv[8];
                #pragma unroll
                for (int u = 0; u < 8; u++) {
                    float v = buf[rloc * 132 + colb + c + u] + bias[rowB0 + colb + c + u];
                    v = fmaxf(v, 0.0f);
                    hv[u] = __float2bfloat16(v);
                    lv[u] = __float2bfloat16(v - __bfloat162float(hv[u]));
                }
                *(uint4*)(hrow + c) = *(uint4*)hv;
                *(uint4*)(lrow + c) = *(uint4*)lv;
            }
        }
    }
}

// ---------------------------------------------------------------------------
// Fused gather + attention per (b,i) row. One CTA of 256 threads per row.
// Emits split-bf16 agg for the final tensor-core GEMM.
// ---------------------------------------------------------------------------
__global__ __launch_bounds__(256) void attn_kernel(
    const float* __restrict__ qh, const float* __restrict__ kvb,
    const float* __restrict__ poskv, const void* __restrict__ idx_raw,
    __nv_bfloat16* __restrict__ agg_hi, __nv_bfloat16* __restrict__ agg_lo)
{
    __shared__ float qv[DHIDDEN];
    __shared__ int   sidx[JJ];
    __shared__ float logit[JJ][HH];
    __shared__ float attnw[JJ][HH];

    const int row = blockIdx.x;       // b*I + i
    const int b   = row >> 11;        // I = 2048
    const int t   = threadIdx.x;

    if (t < JJ) {
        long long n;
        if (g_idx_is64) n = ((const long long*)idx_raw)[(size_t)row * JJ + t];
        else            n = ((const int*)idx_raw)[(size_t)row * JJ + t];
        sidx[t] = b * NKK + (int)n;
    }
    qv[t]       = qh[(size_t)row * DHIDDEN + t];
    qv[t + 256] = qh[(size_t)row * DHIDDEN + t + 256];
    __syncthreads();

    if (t < JJ * HH) {
        int j = t >> 3, h = t & 7;
        const float* kp = kvb   + (size_t)sidx[j] * 1024 + h * 64;
        const float* pp = poskv + ((size_t)row * JJ + j) * 1024 + h * 128;
        const float* qp = qv + h * 64;
        float s = 0.0f;
        #pragma unroll
        for (int d = 0; d < DK; d += 4) {
            float4 kk4 = *(const float4*)(kp + d);
            float4 pk4 = *(const float4*)(pp + d);
            s = fmaf(qp[d + 0], kk4.x + pk4.x, s);
            s = fmaf(qp[d + 1], kk4.y + pk4.y, s);
            s = fmaf(qp[d + 2], kk4.z + pk4.z, s);
            s = fmaf(qp[d + 3], kk4.w + pk4.w, s);
        }
        logit[j][h] = s * 0.125f;
    }
    __syncthreads();

    if (t < HH) {
        float m = -1e30f;
        #pragma unroll
        for (int j = 0; j < JJ; j++) m = fmaxf(m, logit[j][t]);
        float ssum = 0.0f;
        #pragma unroll
        for (int j = 0; j < JJ; j++) {
            float e = expf(logit[j][t] - m);
            attnw[j][t] = e;
            ssum += e;
        }
        float inv = 1.0f / ssum;
        #pragma unroll
        for (int j = 0; j < JJ; j++) attnw[j][t] *= inv;
    }
    __syncthreads();

    #pragma unroll
    for (int o0 = 0; o0 < DHIDDEN; o0 += 256) {
        int o = o0 + t;
        int h = o >> 6, d = o & 63;
        float a = 0.0f;
        #pragma unroll
        for (int j = 0; j < JJ; j++) {
            float w = attnw[j][h];
            float vvv = kvb[(size_t)sidx[j] * 1024 + 512 + h * 64 + d]
                      + poskv[((size_t)row * JJ + j) * 1024 + h * 128 + 64 + d];
            a = fmaf(w, vvv, a);
        }
        __nv_bfloat16 hv = __float2bfloat16(a);
        __nv_bfloat16 lv = __float2bfloat16(a - __bfloat162float(hv));
        agg_hi[(size_t)row * DHIDDEN + o] = hv;
        agg_lo[(size_t)row * DHIDDEN + o] = lv;
    }
}

// ---------------------------------------------------------------------------
// Launch
// inputs: 0:q 1:k 2:pos 3:local_idx 4:Wq 5:Wkv 6:W1 7:b1 8:W2 9:b2 10:Wout
// ---------------------------------------------------------------------------
extern "C" void kernel_launch(void* const* d_in, const int* in_sizes, int n_in,
                              void* d_out, int out_size)
{
    const float* q    = (const float*)d_in[0];
    const float* k    = (const float*)d_in[1];
    const float* pos  = (const float*)d_in[2];
    const void*  lidx = d_in[3];
    const float* Wq   = (const float*)d_in[4];
    const float* Wkv  = (const float*)d_in[5];
    const float* W1   = (const float*)d_in[6];
    const float* b1   = (const float*)d_in[7];
    const float* W2   = (const float*)d_in[8];
    const float* b2   = (const float*)d_in[9];
    const float* Wout = (const float*)d_in[10];
    float* out = (float*)d_out;

    static int smem_set = 0;
    if (!smem_set) {
        cudaFuncSetAttribute(tgemm_kernel,
                             cudaFuncAttributeMaxDynamicSharedMemorySize, TG_SMEM);
        smem_set = 1;
    }

    __nv_bfloat16 *qs_hi, *qs_lo, *ks_hi, *ks_lo, *ps_hi, *ps_lo;
    __nv_bfloat16 *hid_hi, *hid_lo, *agg_hi, *agg_lo, *wt_hi, *wt_lo;
    float *qh, *kv, *poskv;
    cudaGetSymbolAddress((void**)&qs_hi, g_qs_hi);
    cudaGetSymbolAddress((void**)&qs_lo, g_qs_lo);
    cudaGetSymbolAddress((void**)&ks_hi, g_ks_hi);
    cudaGetSymbolAddress((void**)&ks_lo, g_ks_lo);
    cudaGetSymbolAddress((void**)&ps_hi, g_ps_hi);
    cudaGetSymbolAddress((void**)&ps_lo, g_ps_lo);
    cudaGetSymbolAddress((void**)&hid_hi, g_hid_hi);
    cudaGetSymbolAddress((void**)&hid_lo, g_hid_lo);
    cudaGetSymbolAddress((void**)&agg_hi, g_agg_hi);
    cudaGetSymbolAddress((void**)&agg_lo, g_agg_lo);
    cudaGetSymbolAddress((void**)&wt_hi, g_wt_hi);
    cudaGetSymbolAddress((void**)&wt_lo, g_wt_lo);
    cudaGetSymbolAddress((void**)&qh,    g_qh);
    cudaGetSymbolAddress((void**)&kv,    g_kv);
    cudaGetSymbolAddress((void**)&poskv, g_poskv);

    detect_idx_kernel<<<1, 32>>>(lidx);

    // splits
    {
        size_t n4;
        n4 = (size_t)ROWS_BI * DMODEL / 4;
        split_kernel<<<(unsigned)((n4 + 255) / 256), 256>>>(q, qs_hi, qs_lo, n4);
        split_kernel<<<(unsigned)((n4 + 255) / 256), 256>>>(k, ks_hi, ks_lo, n4);
        n4 = (size_t)ROWS_BIJ * DHIDDEN / 4;
        split_kernel<<<(unsigned)((n4 + 255) / 256), 256>>>(pos, ps_hi, ps_lo, n4);
    }
    // weight split+transpose
    splitT_kernel<<<(WQ_SZ + 255) / 256, 256>>>(Wq, wt_hi + WQ_OFF, wt_lo + WQ_OFF,
                                                DMODEL, DHIDDEN);
    splitT_kernel<<<(WKV_SZ + 255) / 256, 256>>>(Wkv, wt_hi + WKV_OFF, wt_lo + WKV_OFF,
                                                 DMODEL, 2 * DHIDDEN);
    splitT_kernel<<<(W1_SZ + 255) / 256, 256>>>(W1, wt_hi + W1_OFF, wt_lo + W1_OFF,
                                                DHIDDEN, DHIDDEN);
    splitT_kernel<<<(W2_SZ + 255) / 256, 256>>>(W2, wt_hi + W2_OFF, wt_lo + W2_OFF,
                                                DHIDDEN, 2 * DHIDDEN);
    splitT_kernel<<<(WOUT_SZ + 255) / 256, 256>>>(Wout, wt_hi + WOUT_OFF, wt_lo + WOUT_OFF,
                                                  DHIDDEN, DMODEL);

    // qh = q @ Wq : M=4096, N=512, K=256, fp32 out
    tgemm_kernel<<<dim3(DHIDDEN / 128, ROWS_BI / 128), 256, TG_SMEM>>>(
        qs_hi, qs_lo, wt_hi + WQ_OFF, wt_lo + WQ_OFF, nullptr,
        qh, nullptr, nullptr, ROWS_BI, DHIDDEN, DMODEL, 0);

    // kv = k @ Wkv : M=4096, N=1024, K=256, fp32 out
    tgemm_kernel<<<dim3(2 * DHIDDEN / 128, ROWS_BI / 128), 256, TG_SMEM>>>(
        ks_hi, ks_lo, wt_hi + WKV_OFF, wt_lo + WKV_OFF, nullptr,
        kv, nullptr, nullptr, ROWS_BI, 2 * DHIDDEN, DMODEL, 0);

    // hidden = relu(pos @ W1 + b1) : M=65536, N=512, K=512, split out
    tgemm_kernel<<<dim3(DHIDDEN / 128, ROWS_BIJ / 128), 256, TG_SMEM>>>(
        ps_hi, ps_lo, wt_hi + W1_OFF, wt_lo + W1_OFF, b1,
        nullptr, hid_hi, hid_lo, ROWS_BIJ, DHIDDEN, DHIDDEN, 1);

    // poskv = hidden @ W2 + b2 : M=65536, N=1024, K=512, fp32 out
    tgemm_kernel<<<dim3(2 * DHIDDEN / 128, ROWS_BIJ / 128), 256, TG_SMEM>>>(
        hid_hi, hid_lo, wt_hi + W2_OFF, wt_lo + W2_OFF, b2,
        poskv, nullptr, nullptr, ROWS_BIJ, 2 * DHIDDEN, DHIDDEN, 0);

    // attention -> agg (split)
    attn_kernel<<<ROWS_BI, 256>>>(qh, kv, poskv, lidx, agg_hi, agg_lo);

    // out = agg @ Wout : M=4096, N=256, K=512, fp32 out
    tgemm_kernel<<<dim3(DMODEL / 128, ROWS_BI / 128), 256, TG_SMEM>>>(
        agg_hi, agg_lo, wt_hi + WOUT_OFF, wt_lo + WOUT_OFF, nullptr,
        out, nullptr, nullptr, ROWS_BI, DMODEL, DHIDDEN, 0);
}